// round 11
// baseline (speedup 1.0000x reference)
#include <cuda_runtime.h>
#include <cstdint>

#define NB   64
#define LL   4500
#define KCH  64

typedef unsigned long long u64;

// ===================== scalar FFMA2 helpers (legacy kernels) ================
__device__ __forceinline__ u64 pk(float lo, float hi) {
    u64 r; asm("mov.b64 %0, {%1,%2};" : "=l"(r) : "f"(lo), "f"(hi)); return r;
}
__device__ __forceinline__ u64 pk1(float v) { return pk(v, v); }
__device__ __forceinline__ void upk(u64 p, float& lo, float& hi) {
    asm("mov.b64 {%0,%1}, %2;" : "=f"(lo), "=f"(hi) : "l"(p));
}
__device__ __forceinline__ u64 f2(u64 a, u64 b, u64 c) {
    u64 d; asm("fma.rn.f32x2 %0, %1, %2, %3;" : "=l"(d) : "l"(a), "l"(b), "l"(c));
    return d;
}

__device__ __forceinline__ float tf32r(float x) {
    unsigned u; asm("cvt.rna.tf32.f32 %0, %1;" : "=r"(u) : "f"(x));
    return __uint_as_float(u);
}

// m16n8k8 tf32 MMA (sm_80+ — assembles for plain compute_103)
#define MMA_T(d, a, b) \
    asm volatile("mma.sync.aligned.m16n8k8.row.col.f32.tf32.tf32.f32 " \
        "{%0,%1,%2,%3}, {%4,%5,%6,%7}, {%8,%9}, {%0,%1,%2,%3};" \
        : "+f"((d)[0]), "+f"((d)[1]), "+f"((d)[2]), "+f"((d)[3]) \
        : "r"((a)[0]), "r"((a)[1]), "r"((a)[2]), "r"((a)[3]), \
          "r"((b)[0]), "r"((b)[1]))

// ===================== scratch ==============================================
__device__ float g_h2[NB * KCH * LL];      // conv2 output (73.7 MB)
__device__ float g_sq[NB * KCH];           // sum_l h2^2
__device__ float g_gram[NB * 64 * 36];     // 8x8 Gram (upper tri) per (n,o)
__device__ float g_weff[NB * 64 * 3 * 64]; // effective weights [n][c][kw][o]
__device__ float g_outb[NB * 64];          // effective bias per (n,o)
__device__ float g_w2im[2 * 320 * 64];     // w2 im2col tf32 {hi,lo}[kcol][n]

// ---------------- K0: zero gram accumulator ---------------------------------
__global__ void k0_zero() {
    int i = blockIdx.x * blockDim.x + threadIdx.x;
    if (i < NB * 64 * 36) g_gram[i] = 0.f;
}

// ---------------- k_prep: w2 -> im2col tf32 hi/lo  B[kcol][n] ---------------
// kcol = c*5 + dk ; value = w2[n][c][dk]
__global__ void k_prep(const float* __restrict__ w2) {
    int t = blockIdx.x * 256 + threadIdx.x;
    if (t >= 20480) return;
    int kcol = t >> 6, nn = t & 63;
    int c = kcol / 5, dk = kcol - c * 5;
    float w  = w2[(nn * 64 + c) * 5 + dk];
    float hi = tf32r(w);
    g_w2im[t]         = hi;
    g_w2im[20480 + t] = tf32r(w - hi);
}

// ---------------- K2: conv1(k=7) + conv2(k=5) via mma.sync tf32 hi/lo --------
// Per block (n, 128-L tile): D[l(128)][k(64)] = sum_{kcol<320} A[l][kcol]*B[kcol][k]
// A[l][kcol] = h1[c][l0+l+dk-2] (c=kcol/5, dk=kcol%5), precomputed hi/lo in smem.
// 8 warps = 4 m-groups x 2 n-groups; warp tile 32l x 32k (2 x 4 m16n8 tiles).
// Phase 0: Bh in smem -> passes Ah*Bh and Al*Bh.  Phase 1: Bl -> Ah*Bl.
#define OF_H1HI 0
#define OF_H1LO 34816
#define OF_BS   69632            /* 320 x 68 floats = 87040 B */
#define OF_XS   156672
#define OF_W1   157248
#define K2_SMEM_BYTES 159040
__global__ __launch_bounds__(256) void k2_mma(const float* __restrict__ x,
                                              const float* __restrict__ w1) {
    extern __shared__ char sm[];
    float* h1hi = (float*)(sm + OF_H1HI);   // [64][136]
    float* h1lo = (float*)(sm + OF_H1LO);   // [64][136]
    float* Bs   = (float*)(sm + OF_BS);     // [320][68]
    float* xs   = (float*)(sm + OF_XS);     // 138
    float* w1s  = (float*)(sm + OF_W1);     // 448

    int tid = threadIdx.x;
    int n = blockIdx.y, l0 = blockIdx.x * 128;

    for (int i = tid; i < 448; i += 256) w1s[i] = w1[i];
    for (int i = tid; i < 138; i += 256) {
        int g = l0 - 5 + i;
        xs[i] = (g >= 0 && g < LL) ? x[n * LL + g] : 0.f;
    }
    __syncthreads();

    // conv1 -> h1 hi/lo tiles (p = 0..131 covers halo 2 both sides)
    for (int i = tid; i < 64 * 132; i += 256) {
        int c = i / 132, p = i - c * 132;
        int g = l0 - 2 + p;
        float a = 0.f;
        if (g >= 0 && g < LL) {
            #pragma unroll
            for (int d = 0; d < 7; d++) a = fmaf(xs[p + d], w1s[c * 7 + d], a);
        }
        float hi = tf32r(a);
        h1hi[c * 136 + p] = hi;
        h1lo[c * 136 + p] = tf32r(a - hi);
    }

    int lane = tid & 31, wid = tid >> 5;
    int r = lane & 3, q = lane >> 2;
    int wm = wid & 3, wn = wid >> 2;
    int mrow  = wm * 32 + q;     // A row base (l within tile)
    int nbase = wn * 32 + q;     // B col base (k)

    float acc[2][4][4];
    #pragma unroll
    for (int mt = 0; mt < 2; mt++)
        #pragma unroll
        for (int nt = 0; nt < 4; nt++)
            #pragma unroll
            for (int v = 0; v < 4; v++) acc[mt][nt][v] = 0.f;

    for (int phase = 0; phase < 2; phase++) {
        if (phase) __syncthreads();          // all reads of previous Bs done
        for (int i = tid; i < 20480; i += 256) {
            int kcol = i >> 6, nn = i & 63;
            Bs[kcol * 68 + nn] = g_w2im[phase * 20480 + i];
        }
        __syncthreads();                     // Bs ready (also covers h1 on phase 0)

        for (int kc = 0; kc < 40; kc++) {
            int col0 = kc * 8 + r;
            int c0 = col0 / 5, d0 = col0 - c0 * 5;
            int col1 = col0 + 4;
            int c1 = col1 / 5, d1 = col1 - c1 * 5;
            int ab0 = c0 * 136 + d0 + mrow;
            int ab1 = c1 * 136 + d1 + mrow;

            unsigned ah[2][4], al[2][4];
            #pragma unroll
            for (int mt = 0; mt < 2; mt++) {
                int o = mt * 16;
                ah[mt][0] = __float_as_uint(h1hi[ab0 + o]);
                ah[mt][1] = __float_as_uint(h1hi[ab0 + o + 8]);
                ah[mt][2] = __float_as_uint(h1hi[ab1 + o]);
                ah[mt][3] = __float_as_uint(h1hi[ab1 + o + 8]);
            }
            if (phase == 0) {
                #pragma unroll
                for (int mt = 0; mt < 2; mt++) {
                    int o = mt * 16;
                    al[mt][0] = __float_as_uint(h1lo[ab0 + o]);
                    al[mt][1] = __float_as_uint(h1lo[ab0 + o + 8]);
                    al[mt][2] = __float_as_uint(h1lo[ab1 + o]);
                    al[mt][3] = __float_as_uint(h1lo[ab1 + o + 8]);
                }
            }
            unsigned bb[4][2];
            int bo = (kc * 8 + r) * 68 + nbase;
            #pragma unroll
            for (int nt = 0; nt < 4; nt++) {
                bb[nt][0] = __float_as_uint(Bs[bo + nt * 8]);
                bb[nt][1] = __float_as_uint(Bs[bo + 4 * 68 + nt * 8]);
            }
            #pragma unroll
            for (int mt = 0; mt < 2; mt++)
                #pragma unroll
                for (int nt = 0; nt < 4; nt++) {
                    MMA_T(acc[mt][nt], ah[mt], bb[nt]);
                    if (phase == 0) MMA_T(acc[mt][nt], al[mt], bb[nt]);
                }
        }
    }

    // epilogue: D[l][k] -> g_h2[n][k][l]
    size_t base = (size_t)n * 64 * LL;
    #pragma unroll
    for (int mt = 0; mt < 2; mt++) {
        int lA = l0 + wm * 32 + mt * 16 + q;
        int lB = lA + 8;
        #pragma unroll
        for (int nt = 0; nt < 4; nt++) {
            int kb = wn * 32 + nt * 8 + 2 * r;
            if (lA < LL) {
                g_h2[base + (size_t)kb * LL + lA]       = acc[mt][nt][0];
                g_h2[base + (size_t)(kb + 1) * LL + lA] = acc[mt][nt][1];
            }
            if (lB < LL) {
                g_h2[base + (size_t)kb * LL + lB]       = acc[mt][nt][2];
                g_h2[base + (size_t)(kb + 1) * LL + lB] = acc[mt][nt][3];
            }
        }
    }
}

// ---------------- k_sq: g_sq[n,k] = sum_l h2^2 -------------------------------
__global__ __launch_bounds__(256) void k_sq() {
    int nk = blockIdx.x;
    const float* p = g_h2 + (size_t)nk * LL;
    float s = 0.f;
    for (int i = threadIdx.x; i < LL / 4; i += 256) {
        float4 v = *(const float4*)(p + i * 4);
        s += v.x * v.x + v.y * v.y + v.z * v.z + v.w * v.w;
    }
    for (int o = 16; o; o >>= 1) s += __shfl_down_sync(0xffffffffu, s, o);
    __shared__ float red[8];
    if ((threadIdx.x & 31) == 0) red[threadIdx.x >> 5] = s;
    __syncthreads();
    if (threadIdx.x == 0) {
        float t = 0.f;
        for (int w = 0; w < 8; w++) t += red[w];
        g_sq[nk] = t;
    }
}

// ---------------- K3: fused squash + psi_mA conv + 8x8 Gram ------------------
__global__ __launch_bounds__(256) void k_gram(const float* __restrict__ w5,
                                              const float* __restrict__ b5) {
    __shared__ float h3s[64 * 132];
    __shared__ u64   ws2[64 * 24];
    __shared__ u64   bpk[64];
    __shared__ float invs[64];
    int n  = blockIdx.y;
    int l0 = blockIdx.x * 128;
    int tid = threadIdx.x;

    if (tid < 64) {
        invs[tid] = 1.f / (1.f + g_sq[n * 64 + tid]);
        bpk[tid]  = pk1(b5[tid]);
    }
    for (int i = tid; i < 64 * 24; i += 256) ws2[i] = pk1(w5[i]);
    __syncthreads();
    for (int i = tid; i < 64 * 130; i += 256) {
        int c = i / 130; int p = i - c * 130;
        int g = l0 - 1 + p;
        h3s[c * 132 + p] = (g >= 0 && g < LL) ? g_h2[((size_t)n*64+c)*LL + g] * invs[c]
                                              : 0.f;
    }
    __syncthreads();

    int o = tid >> 2, lc = tid & 3;
    const u64* wo = ws2 + o * 24;
    u64 bias = bpk[o];

    u64 gr[36];
    #pragma unroll
    for (int p = 0; p < 36; p++) gr[p] = 0ull;

    for (int s = 0; s < 8; s++) {
        int q  = lc + 4 * s;
        int cb = 4 * q;
        u64 vA[8], vB[8];
        #pragma unroll
        for (int i = 0; i < 8; i++) {
            u64 a = bias, b = bias;
            #pragma unroll
            for (int kh = 0; kh < 8; kh++) {
                const float* rp = h3s + (8*i + kh) * 132 + cb;
                u64 u01 = *(const u64*)rp;
                u64 u23 = *(const u64*)(rp + 2);
                u64 u45 = *(const u64*)(rp + 4);
                float d0, c1, c2, c3, c4, d5;
                upk(u01, d0, c1); upk(u23, c2, c3); upk(u45, c4, d5);
                u64 m12 = pk(c1, c2), m34 = pk(c3, c4);
                u64 w0 = wo[kh*3+0], w1 = wo[kh*3+1], w2v = wo[kh*3+2];
                a = f2(w0, u01, a); a = f2(w1, m12, a); a = f2(w2v, u23, a);
                b = f2(w0, u23, b); b = f2(w1, m34, b); b = f2(w2v, u45, b);
            }
            vA[i] = a; vB[i] = b;
        }
        int base = l0 + 4 * q;
        if (base + 3 >= LL) {
            #pragma unroll
            for (int i = 0; i < 8; i++) {
                float a0, a1, b0, b1;
                upk(vA[i], a0, a1); upk(vB[i], b0, b1);
                if (base     >= LL) a0 = 0.f;
                if (base + 1 >= LL) a1 = 0.f;
                if (base + 2 >= LL) b0 = 0.f;
                if (base + 3 >= LL) b1 = 0.f;
                vA[i] = pk(a0, a1); vB[i] = pk(b0, b1);
            }
        }
        int p = 0;
        #pragma unroll
        for (int i = 0; i < 8; i++)
            #pragma unroll
            for (int j = i; j < 8; j++) {
                gr[p] = f2(vA[i], vA[j], gr[p]);
                gr[p] = f2(vB[i], vB[j], gr[p]);
                p++;
            }
    }

    int no = n * 64 + o;
    #pragma unroll
    for (int p = 0; p < 36; p++) {
        float lo, hi; upk(gr[p], lo, hi);
        float v = lo + hi;
        v += __shfl_down_sync(0xffffffffu, v, 2, 4);
        v += __shfl_down_sync(0xffffffffu, v, 1, 4);
        if (lc == 0) atomicAdd(&g_gram[no * 36 + p], v);
    }
}

// ---------------- K4: routing from Gram -> effective weights -----------------
__global__ void k_route(const float* __restrict__ w5, const float* __restrict__ b5) {
    int t = blockIdx.x * 256 + threadIdx.x;
    if (t >= NB * 64) return;
    int n = t >> 6, o = t & 63;

    float G[8][8];
    {
        const float* gp = g_gram + t * 36;
        int p = 0;
        for (int i = 0; i < 8; i++)
            for (int j = i; j < 8; j++) { float v = gp[p++]; G[i][j] = v; G[j][i] = v; }
    }
    float rowsum[8], tot = 0.f;
    for (int i = 0; i < 8; i++) {
        float s = 0.f;
        for (int j = 0; j < 8; j++) s += G[i][j];
        rowsum[i] = s; tot += s;
    }
    float sqn1 = tot * (1.f / 64.f);
    float inv1 = 1.f / (sqn1 + 1.f);
    float b[8], m = -1e30f;
    for (int i = 0; i < 8; i++) {
        b[i] = rowsum[i] * 0.125f * inv1;
        if (b[i] > m) m = b[i];
    }
    float e[8], se = 0.f;
    for (int i = 0; i < 8; i++) { e[i] = expf(b[i] - m); se += e[i]; }
    float ise = 1.f / se;
    float c[8];
    for (int i = 0; i < 8; i++) c[i] = e[i] * ise;
    float sqn2 = 0.f;
    for (int i = 0; i < 8; i++)
        for (int j = 0; j < 8; j++) sqn2 += c[i] * c[j] * G[i][j];
    float k = 1.f / (sqn2 + 1.f);
    float coef[8], csum = 0.f;
    for (int i = 0; i < 8; i++) { coef[i] = c[i] * k; csum += coef[i]; }

    g_outb[t] = csum * b5[o];
    for (int i = 0; i < 8; i++)
        for (int kh = 0; kh < 8; kh++) {
            float cf = coef[i];
            int cc = 8 * i + kh;
            #pragma unroll
            for (int kw = 0; kw < 3; kw++)
                g_weff[(((n * 64 + cc) * 3 + kw) * 64) + o] = cf * w5[o*24 + kh*3 + kw];
        }
}

// ---------------- K5: output conv (64ch -> 64o, k=3, per-n weights) ----------
#define K5_SMEM_FLOATS (64*264 + 12288 + 64 + 64)
__global__ __launch_bounds__(512) void k5_out(float* __restrict__ out) {
    extern __shared__ char sm[];
    float* smf  = (float*)sm;
    float* h3s  = smf;
    float* wsb  = h3s + 64 * 264;
    float* obs  = wsb + 12288;
    float* invs = obs + 64;
    int n  = blockIdx.y;
    int l0 = blockIdx.x * 256;
    int tid = threadIdx.x;

    if (tid < 64) {
        invs[tid] = 1.f / (1.f + g_sq[n * 64 + tid]);
        obs[tid]  = g_outb[n * 64 + tid];
    }
    for (int i = tid; i < 12288; i += 512) wsb[i] = g_weff[n * 12288 + i];
    __syncthreads();
    for (int i = tid; i < 64 * 260; i += 512) {
        int c = i / 260; int p = i - c * 260;
        int g = l0 - 1 + p;
        h3s[c * 264 + p] = (g >= 0 && g < LL) ? g_h2[((size_t)n*64+c)*LL + g] * invs[c]
                                              : 0.f;
    }
    __syncthreads();

    int og = tid >> 5, lg = tid & 31;
    int o0 = og * 4, ll0 = lg * 8;

    u64 ob0 = *(const u64*)(obs + o0);
    u64 ob1 = *(const u64*)(obs + o0 + 2);
    u64 acc[2][8];
    #pragma unroll
    for (int ll = 0; ll < 8; ll++) { acc[0][ll] = ob0; acc[1][ll] = ob1; }

    for (int c = 0; c < 64; c++) {
        const float* hr = h3s + c * 264 + ll0;
        float4 A = *(const float4*)hr;
        float4 B = *(const float4*)(hr + 4);
        float2 C = *(const float2*)(hr + 8);
        float hv[10] = {A.x, A.y, A.z, A.w, B.x, B.y, B.z, B.w, C.x, C.y};
        u64 hp[10];
        #pragma unroll
        for (int t = 0; t < 10; t++) hp[t] = pk1(hv[t]);
        const float* wb = wsb + c * 192;
        #pragma unroll
        for (int kw = 0; kw < 3; kw++) {
            u64 w0 = *(const u64*)(wb + kw * 64 + o0);
            u64 w1 = *(const u64*)(wb + kw * 64 + o0 + 2);
            #pragma unroll
            for (int ll = 0; ll < 8; ll++) {
                acc[0][ll] = f2(w0, hp[ll + kw], acc[0][ll]);
                acc[1][ll] = f2(w1, hp[ll + kw], acc[1][ll]);
            }
        }
    }

    float r[4][8];
    #pragma unroll
    for (int ll = 0; ll < 8; ll++) {
        upk(acc[0][ll], r[0][ll], r[1][ll]);
        upk(acc[1][ll], r[2][ll], r[3][ll]);
    }
    #pragma unroll
    for (int oo = 0; oo < 4; oo++) {
        size_t row = ((size_t)n * 64 + o0 + oo) * LL;
        #pragma unroll
        for (int v = 0; v < 2; v++) {
            int gl = l0 + ll0 + v * 4;
            if (gl < LL) {
                float4 st = {r[oo][v*4+0], r[oo][v*4+1], r[oo][v*4+2], r[oo][v*4+3]};
                *(float4*)&out[row + gl] = st;
            }
        }
    }
}

// ---------------- launch -----------------------------------------------------
extern "C" void kernel_launch(void* const* d_in, const int* in_sizes, int n_in,
                              void* d_out, int out_size) {
    const float *x = nullptr, *w1 = nullptr, *w2 = nullptr, *w5 = nullptr, *b5 = nullptr;
    for (int i = 0; i < n_in; i++) {
        switch (in_sizes[i]) {
            case 288000: x  = (const float*)d_in[i]; break;
            case 448:    w1 = (const float*)d_in[i]; break;
            case 20480:  w2 = (const float*)d_in[i]; break;
            case 1536:   w5 = (const float*)d_in[i]; break;
            case 64:     b5 = (const float*)d_in[i]; break;
        }
    }
    float* out = (float*)d_out;

    const size_t smem5 = K5_SMEM_FLOATS * sizeof(float);   // 117,248 B
    cudaFuncSetAttribute(k2_mma, cudaFuncAttributeMaxDynamicSharedMemorySize,
                         K2_SMEM_BYTES);
    cudaFuncSetAttribute(k5_out, cudaFuncAttributeMaxDynamicSharedMemorySize,
                         (int)smem5);

    k0_zero <<<(NB * 64 * 36 + 255) / 256, 256>>>();
    k_prep  <<<80, 256>>>(w2);
    k2_mma  <<<dim3(36, NB), 256, K2_SMEM_BYTES>>>(x, w1);
    k_sq    <<<NB * KCH, 256>>>();
    k_gram  <<<dim3(36, NB), 256>>>(w5, b5);
    k_route <<<16, 256>>>(w5, b5);
    k5_out  <<<dim3(18, NB), 512, smem5>>>(out);
}